// round 3
// baseline (speedup 1.0000x reference)
#include <cuda_runtime.h>

#define NCAM 6
#define CCH  128
#define H0   32
#define W0   88
#define H1   16
#define W1   44
#define HW0  (H0*W0)      // 2816
#define HW1  (H1*W1)      // 704
#define QDIM 16384
#define PPTS 4
#define EPSF 1e-5f
#define FULLMASK 0xffffffffu
#define TASKS_PER_BLK 8

// Transposed feature scratch: [N, H, W, C] so channel gathers are contiguous.
__device__ float g_f0t[NCAM * HW0 * CCH];   // ~8.65 MB
__device__ float g_f1t[NCAM * HW1 * CCH];   // ~2.16 MB

// -------------------------------------------------------------------------
// SMEM-tiled transpose: per camera n, transpose [C=128, HW] -> [HW, C].
// -------------------------------------------------------------------------
#define NBLK0 (NCAM * 4 * (HW0/32))   // 2112
#define NBLK1 (NCAM * 4 * (HW1/32))   // 528

__global__ void __launch_bounds__(256)
transpose_feats_kernel(const float* __restrict__ f0,
                       const float* __restrict__ f1) {
    __shared__ float tile[32][33];
    int tx = threadIdx.x & 31;
    int ty = threadIdx.x >> 5;            // 0..7

    int b = blockIdx.x;
    const float* __restrict__ src;
    float* __restrict__ dst;
    int n, ct, hwt, HW;
    if (b < NBLK0) {
        n = b / (4 * (HW0/32));
        int r = b % (4 * (HW0/32));
        ct = r & 3;
        hwt = r >> 2;
        src = f0; dst = g_f0t; HW = HW0;
    } else {
        b -= NBLK0;
        n = b / (4 * (HW1/32));
        int r = b % (4 * (HW1/32));
        ct = r & 3;
        hwt = r >> 2;
        src = f1; dst = g_f1t; HW = HW1;
    }

    const float* sp = src + (size_t)n * CCH * HW + (ct*32) * HW + hwt*32;
#pragma unroll
    for (int i = 0; i < 4; i++) {
        int c = ty + i*8;
        tile[c][tx] = sp[c * HW + tx];
    }
    __syncthreads();

    float* dp = dst + (size_t)n * HW * CCH + (hwt*32) * CCH + ct*32;
#pragma unroll
    for (int i = 0; i < 4; i++) {
        int hw = ty + i*8;
        dp[hw * CCH + tx] = tile[tx][hw];
    }
}

// -------------------------------------------------------------------------
// Main sampling kernel: 8 tasks per 256-thread block.
// Phase 1: 48 threads compute (task, cam) projections + bilinear params.
// Phase 2: warp w gathers task w's features; params broadcast via SMEM.
// -------------------------------------------------------------------------
struct __align__(16) SP {
    int4   off;   // 4 corner BYTE offsets into level array
    float4 w;     // 4 bilinear weights (zeroed at borders)
};

__device__ __forceinline__ SP mkparams(float u, float v, int cam, int Wl, int Hl) {
    float px = u * (float)Wl - 0.5f;
    float py = v * (float)Hl - 0.5f;
    float x0f = floorf(px);
    float y0f = floorf(py);
    float wx1 = px - x0f, wx0 = 1.0f - wx1;
    float wy1 = py - y0f, wy0 = 1.0f - wy1;
    int x0 = (int)x0f, y0 = (int)y0f;
    int x1 = x0 + 1,   y1 = y0 + 1;
    // u,v in (0,1) => only -1 underflow / W overflow possible
    if (x0 < 0)      { wx0 = 0.0f; x0 = 0; }
    if (x1 > Wl - 1) { wx1 = 0.0f; x1 = Wl - 1; }
    if (y0 < 0)      { wy0 = 0.0f; y0 = 0; }
    if (y1 > Hl - 1) { wy1 = 0.0f; y1 = Hl - 1; }
    int base = cam * Hl * Wl;
    int r0 = (base + y0 * Wl) * (CCH * 4);   // byte offsets
    int r1 = (base + y1 * Wl) * (CCH * 4);
    int c0 = x0 * (CCH * 4);
    int c1 = x1 * (CCH * 4);
    SP s;
    s.off = make_int4(r0 + c0, r0 + c1, r1 + c0, r1 + c1);
    s.w   = make_float4(wx0 * wy0, wx1 * wy0, wx0 * wy1, wx1 * wy1);
    return s;
}

// Packed f32x2 weighted accumulate of 4 contiguous floats at base+byteoff.
__device__ __forceinline__ void gacc(const char* __restrict__ base, int byteoff,
                                     float w,
                                     unsigned long long& aA, unsigned long long& aB) {
    ulonglong2 v = *reinterpret_cast<const ulonglong2*>(base + byteoff);
    unsigned long long wp;
    asm("mov.b64 %0, {%1, %1};" : "=l"(wp) : "f"(w));
    asm("fma.rn.f32x2 %0, %1, %2, %0;" : "+l"(aA) : "l"(v.x), "l"(wp));
    asm("fma.rn.f32x2 %0, %1, %2, %0;" : "+l"(aB) : "l"(v.y), "l"(wp));
}

__device__ __forceinline__ void gacc4(const char* __restrict__ base, const SP s,
                                      unsigned long long& aA, unsigned long long& aB) {
    gacc(base, s.off.x, s.w.x, aA, aB);
    gacc(base, s.off.y, s.w.y, aA, aB);
    gacc(base, s.off.z, s.w.z, aA, aB);
    gacc(base, s.off.w, s.w.w, aA, aB);
}

__global__ void __launch_bounds__(256)
bev_sample_kernel(const float* __restrict__ refpts,
                  const float* __restrict__ lidar2img,
                  float* __restrict__ out) {
    __shared__ float sM[NCAM * 16];
    __shared__ SP   sP0[TASKS_PER_BLK][NCAM];
    __shared__ SP   sP1[TASKS_PER_BLK][NCAM];
    __shared__ int  sV [TASKS_PER_BLK][NCAM];

    int tid = threadIdx.x;
    if (tid < NCAM * 16) sM[tid] = lidar2img[tid];
    __syncthreads();

    // ---------------- Phase 1: projections -----------------
    if (tid < TASKS_PER_BLK * NCAM) {
        int t   = tid / NCAM;
        int cam = tid - t * NCAM;
        int task = blockIdx.x * TASKS_PER_BLK + t;
        int q = task >> 2;
        int p = task & 3;
        int hb = q >> 7;
        int wb = q & 127;

        // reference_points layout [B=1, P, Hb, Wb, 3]
        const float* rp = refpts + ((size_t)((p * 128 + hb) * 128 + wb)) * 3;
        float X = __ldg(rp + 0) * 102.4f - 51.2f;
        float Y = __ldg(rp + 1) * 102.4f - 51.2f;
        float Z = __ldg(rp + 2) * 8.0f  - 5.0f;

        const float* M = sM + cam * 16;
        float cz = fmaf(M[8], X, fmaf(M[9], Y, fmaf(M[10], Z, M[11])));
        int valid = 0;
        if (cz > EPSF) {
            float cx = fmaf(M[0], X, fmaf(M[1], Y, fmaf(M[2], Z, M[3])));
            float cy = fmaf(M[4], X, fmaf(M[5], Y, fmaf(M[6], Z, M[7])));
            float invz = __fdividef(1.0f, cz);
            float u = cx * invz * (1.0f / 704.0f);
            float v = cy * invz * (1.0f / 256.0f);
            if (u > 0.0f && u < 1.0f && v > 0.0f && v < 1.0f) {
                valid = 1;
                sP0[t][cam] = mkparams(u, v, cam, W0, H0);
                sP1[t][cam] = mkparams(u, v, cam, W1, H1);
            }
        }
        sV[t][cam] = valid;
    }
    __syncthreads();

    // ---------------- Phase 2: gather -----------------
    int warp = tid >> 5;          // task within block
    int lane = tid & 31;

    int flag = (lane < NCAM) ? sV[warp][lane] : 0;
    unsigned vm = __ballot_sync(FULLMASK, flag);
    int cnt = __popc(vm);

    const char* b0 = (const char*)g_f0t + lane * 16;   // lane channel offset
    const char* b1 = (const char*)g_f1t + lane * 16;

    unsigned long long aA = 0ull, aB = 0ull;   // packed fp32x2 accumulators

    while (vm) {
        int cam = __ffs(vm) - 1;
        vm &= vm - 1;
        SP s0 = sP0[warp][cam];    // 2x LDS.128 broadcast
        gacc4(b0, s0, aA, aB);
        SP s1 = sP1[warp][cam];
        gacc4(b1, s1, aA, aB);
    }

    // sampled = (lvl0+lvl1)/2; out = sum / max(cnt,1)
    float scale = 0.5f / fmaxf((float)cnt, 1.0f);
    float ax, ay, az, aw;
    asm("mov.b64 {%0, %1}, %2;" : "=f"(ax), "=f"(ay) : "l"(aA));
    asm("mov.b64 {%0, %1}, %2;" : "=f"(az), "=f"(aw) : "l"(aB));
    float4 o;
    o.x = ax * scale; o.y = ay * scale;
    o.z = az * scale; o.w = aw * scale;

    size_t task = (size_t)blockIdx.x * TASKS_PER_BLK + warp;
    *reinterpret_cast<float4*>(out + task * CCH + lane * 4) = o;
}

extern "C" void kernel_launch(void* const* d_in, const int* in_sizes, int n_in,
                              void* d_out, int out_size) {
    const float* refpts    = (const float*)d_in[0];   // [1,4,128,128,3]
    const float* feats0    = (const float*)d_in[1];   // [1,6,128,32,88]
    const float* feats1    = (const float*)d_in[2];   // [1,6,128,16,44]
    const float* lidar2img = (const float*)d_in[3];   // [1,6,4,4]
    float* out = (float*)d_out;                       // [1,16384,4,128]

    transpose_feats_kernel<<<NBLK0 + NBLK1, 256>>>(feats0, feats1);
    bev_sample_kernel<<<(QDIM * PPTS) / TASKS_PER_BLK, 256>>>(refpts, lidar2img, out);
}

// round 4
// speedup vs baseline: 1.1604x; 1.1604x over previous
#include <cuda_runtime.h>

#define NCAM 6
#define CCH  128
#define H0   32
#define W0   88
#define H1   16
#define W1   44
#define HW0  (H0*W0)      // 2816
#define HW1  (H1*W1)      // 704
#define QDIM 16384
#define PPTS 4
#define NTASK (QDIM * PPTS)
#define EPSF 1e-5f
#define FULLMASK 0xffffffffu

// Transposed feature scratch: [N, H, W, C] so channel gathers are contiguous.
__device__ float g_f0t[NCAM * HW0 * CCH];   // ~8.65 MB
__device__ float g_f1t[NCAM * HW1 * CCH];   // ~2.16 MB

// Per-(task, valid-cam) sampling records + per-task counts.
struct __align__(16) SP {
    int4   off;   // 4 corner BYTE offsets into level array
    float4 w;     // 4 bilinear weights (zeroed at borders)
};
struct __align__(16) Rec { SP s0; SP s1; };   // 64 B

__device__ Rec g_rec[NTASK * NCAM];          // 25.2 MB
__device__ int g_cnt[NTASK];

// -------------------------------------------------------------------------
// SMEM-tiled transpose: per camera n, transpose [C=128, HW] -> [HW, C].
// -------------------------------------------------------------------------
#define NBLK0 (NCAM * 4 * (HW0/32))   // 2112
#define NBLK1 (NCAM * 4 * (HW1/32))   // 528

__global__ void __launch_bounds__(256)
transpose_feats_kernel(const float* __restrict__ f0,
                       const float* __restrict__ f1) {
    __shared__ float tile[32][33];
    int tx = threadIdx.x & 31;
    int ty = threadIdx.x >> 5;

    int b = blockIdx.x;
    const float* __restrict__ src;
    float* __restrict__ dst;
    int n, ct, hwt, HW;
    if (b < NBLK0) {
        n = b / (4 * (HW0/32));
        int r = b % (4 * (HW0/32));
        ct = r & 3; hwt = r >> 2;
        src = f0; dst = g_f0t; HW = HW0;
    } else {
        b -= NBLK0;
        n = b / (4 * (HW1/32));
        int r = b % (4 * (HW1/32));
        ct = r & 3; hwt = r >> 2;
        src = f1; dst = g_f1t; HW = HW1;
    }

    const float* sp = src + (size_t)n * CCH * HW + (ct*32) * HW + hwt*32;
#pragma unroll
    for (int i = 0; i < 4; i++) {
        int c = ty + i*8;
        tile[c][tx] = sp[c * HW + tx];
    }
    __syncthreads();

    float* dp = dst + (size_t)n * HW * CCH + (hwt*32) * CCH + ct*32;
#pragma unroll
    for (int i = 0; i < 4; i++) {
        int hw = ty + i*8;
        dp[hw * CCH + tx] = tile[tx][hw];
    }
}

// -------------------------------------------------------------------------
// Kernel A: projection + compaction. 8 lanes per task (lanes 0-5 = cams).
// -------------------------------------------------------------------------
__device__ __forceinline__ SP mkparams(float u, float v, int cam, int Wl, int Hl) {
    float px = u * (float)Wl - 0.5f;
    float py = v * (float)Hl - 0.5f;
    float x0f = floorf(px);
    float y0f = floorf(py);
    float wx1 = px - x0f, wx0 = 1.0f - wx1;
    float wy1 = py - y0f, wy0 = 1.0f - wy1;
    int x0 = (int)x0f, y0 = (int)y0f;
    int x1 = x0 + 1,   y1 = y0 + 1;
    if (x0 < 0)      { wx0 = 0.0f; x0 = 0; }
    if (x1 > Wl - 1) { wx1 = 0.0f; x1 = Wl - 1; }
    if (y0 < 0)      { wy0 = 0.0f; y0 = 0; }
    if (y1 > Hl - 1) { wy1 = 0.0f; y1 = Hl - 1; }
    int base = cam * Hl * Wl;
    int r0 = (base + y0 * Wl) * (CCH * 4);   // byte offsets
    int r1 = (base + y1 * Wl) * (CCH * 4);
    int c0 = x0 * (CCH * 4);
    int c1 = x1 * (CCH * 4);
    SP s;
    s.off = make_int4(r0 + c0, r0 + c1, r1 + c0, r1 + c1);
    s.w   = make_float4(wx0 * wy0, wx1 * wy0, wx0 * wy1, wx1 * wy1);
    return s;
}

__global__ void __launch_bounds__(256)
project_kernel(const float* __restrict__ refpts,
               const float* __restrict__ lidar2img) {
    __shared__ float sM[NCAM * 16];
    if (threadIdx.x < NCAM * 16) sM[threadIdx.x] = lidar2img[threadIdx.x];
    __syncthreads();

    int gthread = blockIdx.x * 256 + threadIdx.x;
    int lane = threadIdx.x & 31;
    int sub  = lane & 7;                     // 0..7; 0..5 = cam
    int task = gthread >> 3;                 // 8 lanes per task
    if (task >= NTASK) return;

    int q = task >> 2;
    int p = task & 3;
    int hb = q >> 7;
    int wb = q & 127;
    const float* rp = refpts + ((size_t)((p * 128 + hb) * 128 + wb)) * 3;
    float X = __ldg(rp + 0) * 102.4f - 51.2f;
    float Y = __ldg(rp + 1) * 102.4f - 51.2f;
    float Z = __ldg(rp + 2) * 8.0f  - 5.0f;

    bool valid = false;
    float u = 0.f, v = 0.f;
    if (sub < NCAM) {
        const float* M = sM + sub * 16;
        float cz = fmaf(M[8], X, fmaf(M[9], Y, fmaf(M[10], Z, M[11])));
        if (cz > EPSF) {
            float cx = fmaf(M[0], X, fmaf(M[1], Y, fmaf(M[2], Z, M[3])));
            float cy = fmaf(M[4], X, fmaf(M[5], Y, fmaf(M[6], Z, M[7])));
            float invz = __fdividef(1.0f, cz);
            u = cx * invz * (1.0f / 704.0f);
            v = cy * invz * (1.0f / 256.0f);
            valid = (u > 0.0f) & (u < 1.0f) & (v > 0.0f) & (v < 1.0f);
        }
    }

    unsigned m = __ballot_sync(FULLMASK, valid);
    int g = lane >> 3;
    unsigned gm = (m >> (g * 8)) & 0xFFu;

    if (sub == 6) g_cnt[task] = __popc(gm);

    if (valid) {
        int slot = __popc(gm & ((1u << sub) - 1u));
        Rec r;
        r.s0 = mkparams(u, v, sub, W0, H0);
        r.s1 = mkparams(u, v, sub, W1, H1);
        Rec* dst = g_rec + task * NCAM + slot;
        int4* d4 = reinterpret_cast<int4*>(dst);
        d4[0] = r.s0.off;
        d4[1] = *reinterpret_cast<int4*>(&r.s0.w);
        d4[2] = r.s1.off;
        d4[3] = *reinterpret_cast<int4*>(&r.s1.w);
    }
}

// -------------------------------------------------------------------------
// Kernel B: pure gather. 1 warp per task; lane owns 4 channels.
// -------------------------------------------------------------------------
__device__ __forceinline__ void gacc(const char* __restrict__ base, int byteoff,
                                     float w,
                                     unsigned long long& aA, unsigned long long& aB) {
    ulonglong2 v = *reinterpret_cast<const ulonglong2*>(base + byteoff);
    unsigned long long wp;
    asm("mov.b64 %0, {%1, %1};" : "=l"(wp) : "f"(w));
    asm("fma.rn.f32x2 %0, %1, %2, %0;" : "+l"(aA) : "l"(v.x), "l"(wp));
    asm("fma.rn.f32x2 %0, %1, %2, %0;" : "+l"(aB) : "l"(v.y), "l"(wp));
}

__device__ __forceinline__ void gacc4(const char* __restrict__ base,
                                      int4 off, float4 w,
                                      unsigned long long& aA, unsigned long long& aB) {
    gacc(base, off.x, w.x, aA, aB);
    gacc(base, off.y, w.y, aA, aB);
    gacc(base, off.z, w.z, aA, aB);
    gacc(base, off.w, w.w, aA, aB);
}

__global__ void __launch_bounds__(256)
gather_kernel(float* __restrict__ out) {
    int warp = blockIdx.x * 8 + (threadIdx.x >> 5);
    int lane = threadIdx.x & 31;
    int task = warp;

    int cnt = __ldg(g_cnt + task);

    const char* b0 = (const char*)g_f0t + lane * 16;
    const char* b1 = (const char*)g_f1t + lane * 16;
    const int4* rec = reinterpret_cast<const int4*>(g_rec + task * NCAM);

    unsigned long long aA = 0ull, aB = 0ull;

    for (int i = 0; i < cnt; i++) {
        int4   o0 = __ldg(rec + i*4 + 0);            // uniform broadcasts
        float4 w0 = *(const float4*)&(__ldg(rec + i*4 + 1));
        int4   o1 = __ldg(rec + i*4 + 2);
        float4 w1 = *(const float4*)&(__ldg(rec + i*4 + 3));
        gacc4(b0, o0, w0, aA, aB);
        gacc4(b1, o1, w1, aA, aB);
    }

    float scale = 0.5f / fmaxf((float)cnt, 1.0f);
    float ax, ay, az, aw;
    asm("mov.b64 {%0, %1}, %2;" : "=f"(ax), "=f"(ay) : "l"(aA));
    asm("mov.b64 {%0, %1}, %2;" : "=f"(az), "=f"(aw) : "l"(aB));
    float4 o;
    o.x = ax * scale; o.y = ay * scale;
    o.z = az * scale; o.w = aw * scale;
    *reinterpret_cast<float4*>(out + (size_t)task * CCH + lane * 4) = o;
}

extern "C" void kernel_launch(void* const* d_in, const int* in_sizes, int n_in,
                              void* d_out, int out_size) {
    const float* refpts    = (const float*)d_in[0];   // [1,4,128,128,3]
    const float* feats0    = (const float*)d_in[1];   // [1,6,128,32,88]
    const float* feats1    = (const float*)d_in[2];   // [1,6,128,16,44]
    const float* lidar2img = (const float*)d_in[3];   // [1,6,4,4]
    float* out = (float*)d_out;                       // [1,16384,4,128]

    transpose_feats_kernel<<<NBLK0 + NBLK1, 256>>>(feats0, feats1);
    project_kernel<<<(NTASK * 8) / 256, 256>>>(refpts, lidar2img);
    gather_kernel<<<NTASK / 8, 256>>>(out);
}

// round 5
// speedup vs baseline: 1.5023x; 1.2947x over previous
#include <cuda_runtime.h>

#define NCAM 6
#define CCH  128
#define H0   32
#define W0   88
#define H1   16
#define W1   44
#define HW0  (H0*W0)      // 2816
#define HW1  (H1*W1)      // 704
#define QDIM 16384
#define PPTS 4
#define NTASK (QDIM * PPTS)
#define EPSF 1e-5f
#define FULLMASK 0xffffffffu

// Transposed feature scratch: [N, H, W, C] so channel gathers are contiguous.
__device__ float g_f0t[NCAM * HW0 * CCH];   // ~8.65 MB
__device__ float g_f1t[NCAM * HW1 * CCH];   // ~2.16 MB

// -------------------------------------------------------------------------
// SMEM-tiled transpose: per camera n, transpose [C=128, HW] -> [HW, C].
// -------------------------------------------------------------------------
#define NBLK0 (NCAM * 4 * (HW0/32))   // 2112
#define NBLK1 (NCAM * 4 * (HW1/32))   // 528

__global__ void __launch_bounds__(256)
transpose_feats_kernel(const float* __restrict__ f0,
                       const float* __restrict__ f1) {
    __shared__ float tile[32][33];
    int tx = threadIdx.x & 31;
    int ty = threadIdx.x >> 5;

    int b = blockIdx.x;
    const float* __restrict__ src;
    float* __restrict__ dst;
    int n, ct, hwt, HW;
    if (b < NBLK0) {
        n = b / (4 * (HW0/32));
        int r = b % (4 * (HW0/32));
        ct = r & 3; hwt = r >> 2;
        src = f0; dst = g_f0t; HW = HW0;
    } else {
        b -= NBLK0;
        n = b / (4 * (HW1/32));
        int r = b % (4 * (HW1/32));
        ct = r & 3; hwt = r >> 2;
        src = f1; dst = g_f1t; HW = HW1;
    }

    const float* sp = src + (size_t)n * CCH * HW + (ct*32) * HW + hwt*32;
#pragma unroll
    for (int i = 0; i < 4; i++) {
        int c = ty + i*8;
        tile[c][tx] = sp[c * HW + tx];
    }
    __syncthreads();

    float* dp = dst + (size_t)n * HW * CCH + (hwt*32) * CCH + ct*32;
#pragma unroll
    for (int i = 0; i < 4; i++) {
        int hw = ty + i*8;
        dp[hw * CCH + tx] = tile[tx][hw];
    }
}

// -------------------------------------------------------------------------
// Main sampling kernel: 1 warp per task; lane owns 4 channels.
// Lanes 0-5 project (u,v,valid); per valid cam, shuffle only u,v and let all
// lanes recompute bilinear params (warp-uniform math, low reg pressure).
// -------------------------------------------------------------------------

// Packed f32x2 weighted accumulate of 4 contiguous floats at base+byteoff.
__device__ __forceinline__ void gacc(const char* __restrict__ base, int byteoff,
                                     float w,
                                     unsigned long long& aA, unsigned long long& aB) {
    ulonglong2 v = *reinterpret_cast<const ulonglong2*>(base + byteoff);
    unsigned long long wp;
    asm("mov.b64 %0, {%1, %1};" : "=l"(wp) : "f"(w));
    asm("fma.rn.f32x2 %0, %1, %2, %0;" : "+l"(aA) : "l"(v.x), "l"(wp));
    asm("fma.rn.f32x2 %0, %1, %2, %0;" : "+l"(aB) : "l"(v.y), "l"(wp));
}

// Inline bilinear sample of one level; u,v warp-uniform.
__device__ __forceinline__ void sample_level(const char* __restrict__ base,
                                             float u, float v, int cam,
                                             int Wl, int Hl,
                                             unsigned long long& aA,
                                             unsigned long long& aB) {
    float px = u * (float)Wl - 0.5f;
    float py = v * (float)Hl - 0.5f;
    float x0f = floorf(px);
    float y0f = floorf(py);
    float wx1 = px - x0f, wx0 = 1.0f - wx1;
    float wy1 = py - y0f, wy0 = 1.0f - wy1;
    int x0 = (int)x0f, y0 = (int)y0f;
    int x1 = x0 + 1,   y1 = y0 + 1;
    // u,v in (0,1) => only -1 underflow / W overflow possible
    if (x0 < 0)      { wx0 = 0.0f; x0 = 0; }
    if (x1 > Wl - 1) { wx1 = 0.0f; x1 = Wl - 1; }
    if (y0 < 0)      { wy0 = 0.0f; y0 = 0; }
    if (y1 > Hl - 1) { wy1 = 0.0f; y1 = Hl - 1; }
    int cambase = cam * Hl * Wl;
    int r0 = (cambase + y0 * Wl) * (CCH * 4);   // byte offsets
    int r1 = (cambase + y1 * Wl) * (CCH * 4);
    int c0 = x0 * (CCH * 4);
    int c1 = x1 * (CCH * 4);
    gacc(base, r0 + c0, wx0 * wy0, aA, aB);
    gacc(base, r0 + c1, wx1 * wy0, aA, aB);
    gacc(base, r1 + c0, wx0 * wy1, aA, aB);
    gacc(base, r1 + c1, wx1 * wy1, aA, aB);
}

__global__ void __launch_bounds__(256, 8)
bev_sample_kernel(const float* __restrict__ refpts,
                  const float* __restrict__ lidar2img,
                  float* __restrict__ out) {
    __shared__ float sM[NCAM * 16];
    if (threadIdx.x < NCAM * 16) sM[threadIdx.x] = lidar2img[threadIdx.x];
    __syncthreads();

    int warp = blockIdx.x * 8 + (threadIdx.x >> 5);
    int lane = threadIdx.x & 31;
    int task = warp;

    int q = task >> 2;
    int p = task & 3;
    int hb = q >> 7;
    int wb = q & 127;

    // reference_points layout [B=1, P, Hb, Wb, 3] — uniform per warp
    const float* rp = refpts + ((size_t)((p * 128 + hb) * 128 + wb)) * 3;
    float X = __ldg(rp + 0) * 102.4f - 51.2f;
    float Y = __ldg(rp + 1) * 102.4f - 51.2f;
    float Z = __ldg(rp + 2) * 8.0f  - 5.0f;

    // Lanes 0-5 each compute one camera's (u, v, valid)
    bool valid = false;
    float u = 0.f, v = 0.f;
    if (lane < NCAM) {
        const float* M = sM + lane * 16;
        float cz = fmaf(M[8], X, fmaf(M[9], Y, fmaf(M[10], Z, M[11])));
        if (cz > EPSF) {
            float cx = fmaf(M[0], X, fmaf(M[1], Y, fmaf(M[2], Z, M[3])));
            float cy = fmaf(M[4], X, fmaf(M[5], Y, fmaf(M[6], Z, M[7])));
            float invz = __fdividef(1.0f, cz);
            u = cx * invz * (1.0f / 704.0f);
            v = cy * invz * (1.0f / 256.0f);
            valid = (u > 0.0f) & (u < 1.0f) & (v > 0.0f) & (v < 1.0f);
        }
    }

    unsigned vm = __ballot_sync(FULLMASK, valid) & 0x3Fu;
    int cnt = __popc(vm);

    const char* b0 = (const char*)g_f0t + lane * 16;   // lane channel offset
    const char* b1 = (const char*)g_f1t + lane * 16;

    unsigned long long aA = 0ull, aB = 0ull;   // packed fp32x2 accumulators

    while (vm) {
        int cam = __ffs(vm) - 1;
        vm &= vm - 1;
        float uu = __shfl_sync(FULLMASK, u, cam);
        float vv = __shfl_sync(FULLMASK, v, cam);
        sample_level(b0, uu, vv, cam, W0, H0, aA, aB);
        sample_level(b1, uu, vv, cam, W1, H1, aA, aB);
    }

    // sampled = (lvl0+lvl1)/2; out = sum / max(cnt,1)
    float scale = 0.5f / fmaxf((float)cnt, 1.0f);
    float ax, ay, az, aw;
    asm("mov.b64 {%0, %1}, %2;" : "=f"(ax), "=f"(ay) : "l"(aA));
    asm("mov.b64 {%0, %1}, %2;" : "=f"(az), "=f"(aw) : "l"(aB));
    float4 o;
    o.x = ax * scale; o.y = ay * scale;
    o.z = az * scale; o.w = aw * scale;
    *reinterpret_cast<float4*>(out + (size_t)task * CCH + lane * 4) = o;
}

extern "C" void kernel_launch(void* const* d_in, const int* in_sizes, int n_in,
                              void* d_out, int out_size) {
    const float* refpts    = (const float*)d_in[0];   // [1,4,128,128,3]
    const float* feats0    = (const float*)d_in[1];   // [1,6,128,32,88]
    const float* feats1    = (const float*)d_in[2];   // [1,6,128,16,44]
    const float* lidar2img = (const float*)d_in[3];   // [1,6,4,4]
    float* out = (float*)d_out;                       // [1,16384,4,128]

    transpose_feats_kernel<<<NBLK0 + NBLK1, 256>>>(feats0, feats1);
    bev_sample_kernel<<<NTASK / 8, 256>>>(refpts, lidar2img, out);
}